// round 1
// baseline (speedup 1.0000x reference)
#include <cuda_runtime.h>
#include <cstdint>

// Problem constants (fixed by the reference setup)
#define BB 32
#define SS 32
#define AA 512
#define VOCAB 32000

// ---------------------------------------------------------------------------
// Kernel 1: out = decoder_outputs, with out[:, :, 1] = 0 fused in.
// float4 copy. VOCAB = 32000 is divisible by 4, and element v==1 of each
// (b,s) row is the .y lane of the float4 whose row-local float4 index is 0.
// Total float4s: 32*32*32000/4 = 8,192,000.
// ---------------------------------------------------------------------------
__global__ void __launch_bounds__(256)
pg_copy_zero_kernel(const float4* __restrict__ src, float4* __restrict__ dst) {
    const int n4_per_row = VOCAB / 4;           // 8000
    int idx = blockIdx.x * blockDim.x + threadIdx.x;
    // grid sized exactly: 8,192,000 / 256 = 32000 blocks, no bounds check needed
    float4 v = src[idx];
    if ((idx % n4_per_row) == 0) v.y = 0.0f;    // zero vocab index 1 of this row
    dst[idx] = v;
}

// ---------------------------------------------------------------------------
// Kernel 2: scatter-max.
// One thread per (b, a). m = convert_table[input_sequence[b,a]].
// Skip m == 1 (its final value is forced to 0 anyway, so skipping makes the
// "zero col 1 after max" ordering equivalent to our fused "zero in copy").
// All values are in [0,1) -> non-negative floats -> signed int atomicMax on
// the IEEE bit pattern is exact and monotone.
// att[(b*S+s)*A + a]: within a warp, a is consecutive -> coalesced per s.
// ---------------------------------------------------------------------------
__global__ void __launch_bounds__(256)
pg_scatter_kernel(const float* __restrict__ att,
                  const int*   __restrict__ seq,
                  const int*   __restrict__ table,
                  float*       __restrict__ out) {
    int tid = blockIdx.x * blockDim.x + threadIdx.x;   // 0 .. B*A-1 = 16383
    int b = tid / AA;
    int a = tid - b * AA;

    int tok = seq[tid];            // [0, 50000)
    int m   = table[tok];          // [0, VOCAB)

    if (m != 1) {
        const float* att_ba = att + (size_t)b * SS * AA + a;
        int* out_bm = (int*)(out + (size_t)b * SS * VOCAB + m);
        #pragma unroll
        for (int s = 0; s < SS; s++) {
            float v = att_ba[(size_t)s * AA];
            atomicMax(out_bm + (size_t)s * VOCAB, __float_as_int(v));
        }
    }
}

// ---------------------------------------------------------------------------
// Launch
// Inputs (metadata order):
//   d_in[0] decoder_outputs  f32 [B,S,VOCAB]
//   d_in[1] attention_scores f32 [B,S,A]
//   d_in[2] input_sequence   i32 [B,A]
//   d_in[3] repeat_idx       i32 [S,1]   (unused)
//   d_in[4] repeat_idx2      i32 [B,1]   (unused)
//   d_in[5] convert_table    i32 [SRC_VOCAB]
// Output: f32 [B,S,VOCAB]
// ---------------------------------------------------------------------------
extern "C" void kernel_launch(void* const* d_in, const int* in_sizes, int n_in,
                              void* d_out, int out_size) {
    const float4* dec = (const float4*)d_in[0];
    const float*  att = (const float*)d_in[1];
    const int*    seq = (const int*)d_in[2];
    const int*    tbl = (const int*)d_in[5];
    float*        out = (float*)d_out;

    const int n4 = BB * SS * VOCAB / 4;      // 8,192,000
    pg_copy_zero_kernel<<<n4 / 256, 256>>>(dec, (float4*)out);

    const int nba = BB * AA;                 // 16384
    pg_scatter_kernel<<<nba / 256, 256>>>(att, seq, tbl, out);
}